// round 15
// baseline (speedup 1.0000x reference)
#include <cuda_runtime.h>
#include <cuda_fp16.h>
#include <cstdint>
#include <cstddef>

#define NN   50000
#define NE   640000
#define INF_ 512
#define HIDF 128
#define NG   256

// ---------------- device scratch (no allocations allowed) ----------------
__device__ int   g_cnt[NN];          // zero at load; k_scan restores to zero each launch
__device__ float g_dinv[NN];
__device__ int   g_rowptr[NN + 1];
__device__ int   g_rank[NE];
__device__ int   g_src[NE];
__device__ __half g_g1[(size_t)NN * HIDF];    // gemm outputs (fp16), reused both layers
__device__ __half g_h1h[(size_t)NN * HIDF];   // layer-1 agg output (fp16)
// transposed fp16 weights: Wt[n][k] = W[k][n]
__device__ __half g_w1h[128 * 512];
__device__ __half g_w2h[128 * 128];

// ---------------- helpers ----------------
__device__ __forceinline__ uint32_t smem_u32(const void* p) {
    uint32_t a;
    asm("{ .reg .u64 t; cvta.to.shared.u64 t, %1; cvt.u32.u64 %0, t; }" : "=r"(a) : "l"(p));
    return a;
}
__device__ __forceinline__ void ldsm_x4(uint32_t& r0, uint32_t& r1, uint32_t& r2, uint32_t& r3,
                                        uint32_t addr) {
    asm volatile("ldmatrix.sync.aligned.m8n8.x4.shared.b16 {%0,%1,%2,%3}, [%4];"
                 : "=r"(r0), "=r"(r1), "=r"(r2), "=r"(r3) : "r"(addr));
}
__device__ __forceinline__ void mma_f16(float* c, const uint32_t* a, const uint32_t* b) {
    asm volatile(
        "mma.sync.aligned.m16n8k16.row.col.f32.f16.f16.f32 "
        "{%0,%1,%2,%3}, {%4,%5,%6,%7}, {%8,%9}, {%0,%1,%2,%3};"
        : "+f"(c[0]), "+f"(c[1]), "+f"(c[2]), "+f"(c[3])
        : "r"(a[0]), "r"(a[1]), "r"(a[2]), "r"(a[3]), "r"(b[0]), "r"(b[1]));
}

// ---------------- preprocessing ----------------
// transpose/cast weights; consecutive threads read consecutive W elements
__global__ void k_prepw(const float* __restrict__ W1, const float* __restrict__ W2) {
    int i = blockIdx.x * blockDim.x + threadIdx.x;
    if (i < 128 * 512) {
        int k = i >> 7, n = i & 127;
        g_w1h[n * 512 + k] = __float2half_rn(W1[i]);
    }
    if (i < 128 * 128) {
        int k = i >> 7, n = i & 127;
        g_w2h[n * 128 + k] = __float2half_rn(W2[i]);
    }
}

// count + record per-edge rank within destination (atomicAdd return value), 2 edges/thread
__global__ void k_count(const int* __restrict__ col) {
    int t = blockIdx.x * blockDim.x + threadIdx.x;
    if (t < NE / 2) {
        int2 c2 = ((const int2*)col)[t];
        int2 r;
        r.x = atomicAdd(&g_cnt[c2.x], 1);
        r.y = atomicAdd(&g_cnt[c2.y], 1);
        ((int2*)g_rank)[t] = r;
    }
}

// single-block scan, smem-staged for fully coalesced global access.
// Also restores g_cnt to zero for the next launch (invariant: zero at entry).
__global__ __launch_bounds__(1024) void k_scan() {
    extern __shared__ int sc[];   // NN ints = 200 000 B
    __shared__ int wsum[32];
    int t = threadIdx.x, lane = t & 31, w = t >> 5;
    for (int i = t; i < NN; i += 1024) {
        int c = g_cnt[i];
        sc[i] = c;
        g_dinv[i] = rsqrtf((float)(c + 1));  // +1 self-loop
        g_cnt[i] = 0;                        // restore invariant for next launch
    }
    __syncthreads();
    const int SEG = (NN + 1023) / 1024;  // 49
    int s0 = t * SEG, s1 = s0 + SEG;
    if (s1 > NN) s1 = NN;
    if (s0 > NN) s0 = NN;
    int s = 0;
    for (int i = s0; i < s1; i++) s += sc[i];
    int v = s;
    #pragma unroll
    for (int o = 1; o < 32; o <<= 1) {
        int u = __shfl_up_sync(0xFFFFFFFFu, v, o);
        if (lane >= o) v += u;
    }
    if (lane == 31) wsum[w] = v;
    __syncthreads();
    if (w == 0) {
        int x = wsum[lane];
        #pragma unroll
        for (int o = 1; o < 32; o <<= 1) {
            int u = __shfl_up_sync(0xFFFFFFFFu, x, o);
            if (lane >= o) x += u;
        }
        wsum[lane] = x;
    }
    __syncthreads();
    int P = v - s + (w > 0 ? wsum[w - 1] : 0);
    for (int i = s0; i < s1; i++) {
        int c = sc[i];
        sc[i] = P;     // in-place exclusive prefix
        P += c;
    }
    __syncthreads();
    for (int i = t; i < NN; i += 1024) g_rowptr[i] = sc[i];
    if (t == 0) g_rowptr[NN] = wsum[31];
}

// atomic-free fill using precomputed ranks, 2 edges/thread
__global__ void k_fill(const int* __restrict__ row, const int* __restrict__ col) {
    int t = blockIdx.x * blockDim.x + threadIdx.x;
    if (t < NE / 2) {
        int2 r2 = ((const int2*)row)[t];
        int2 c2 = ((const int2*)col)[t];
        int2 k2 = ((const int2*)g_rank)[t];
        g_src[g_rowptr[c2.x] + k2.x] = r2.x;
        g_src[g_rowptr[c2.y] + k2.y] = r2.y;
    }
}

// ---------------- HMMA GEMM: C[M,128] = A[M,K] @ Wt^T, fp16 out ----------------
// Double-buffered smem: one __syncthreads per K-chunk.
#define ASTRIDE 40  // fp16 elems per smem row (80 B), conflict-free ldmatrix

template <bool F32A>
__device__ __forceinline__ void gemm_body(const void* __restrict__ Aptr,
                                          const __half* __restrict__ Bh,
                                          __half* __restrict__ C,
                                          int M, int K) {
    __shared__ __half sAh[2][128 * ASTRIDE];
    __shared__ __half sBh[2][128 * ASTRIDE];
    const int tid = threadIdx.x;
    const int wid = tid >> 5, lane = tid & 31;
    const int wm = (wid >> 1) * 32;
    const int wn = (wid & 1) * 64;
    const int g = lane >> 2, tig = lane & 3;
    const int row0 = blockIdx.x * 128;

    const uint32_t uA0 = smem_u32(sAh[0]), uA1 = smem_u32(sAh[1]);
    const uint32_t uB0 = smem_u32(sBh[0]), uB1 = smem_u32(sBh[1]);

    float c[2][8][4];
    #pragma unroll
    for (int mt = 0; mt < 2; mt++)
        #pragma unroll
        for (int nt = 0; nt < 8; nt++)
            #pragma unroll
            for (int q = 0; q < 4; q++) c[mt][nt][q] = 0.f;

    const int nch = K >> 5;

    float4 pa[4];
    uint4 pah[2];
    uint4 pbh[2];

    // ---- load chunk 0 into regs ----
    if (F32A) {
        const float* A = (const float*)Aptr;
        #pragma unroll
        for (int i = 0; i < 4; i++) {
            int q = i * 256 + tid;
            int r = q >> 3, c4 = q & 7;
            int gr = row0 + r;
            pa[i] = (gr < M) ? *(const float4*)(A + (size_t)gr * K + c4 * 4)
                             : make_float4(0.f, 0.f, 0.f, 0.f);
        }
    } else {
        const __half* Ah = (const __half*)Aptr;
        #pragma unroll
        for (int i = 0; i < 2; i++) {
            int q = i * 256 + tid;
            int r = q >> 2, c16 = q & 3;
            int gr = row0 + r;
            pah[i] = (gr < M) ? *(const uint4*)(Ah + (size_t)gr * K + c16 * 8)
                              : make_uint4(0, 0, 0, 0);
        }
    }
    #pragma unroll
    for (int i = 0; i < 2; i++) {
        int q = i * 256 + tid;
        int r = q >> 2, c16 = q & 3;
        pbh[i] = *(const uint4*)(Bh + (size_t)r * K + c16 * 8);
    }

    // ---- store chunk 0 into stage 0; single barrier ----
    {
        __half* dA = sAh[0];
        __half* dB = sBh[0];
        if (F32A) {
            #pragma unroll
            for (int i = 0; i < 4; i++) {
                int q = i * 256 + tid;
                int r = q >> 3, c4 = q & 7;
                float4 v = pa[i];
                __half2 h0 = __floats2half2_rn(v.x, v.y);
                __half2 h1 = __floats2half2_rn(v.z, v.w);
                int e = r * ASTRIDE + c4 * 4;
                *(uint32_t*)((char*)dA + e * 2)     = *(uint32_t*)&h0;
                *(uint32_t*)((char*)dA + e * 2 + 4) = *(uint32_t*)&h1;
            }
        } else {
            #pragma unroll
            for (int i = 0; i < 2; i++) {
                int q = i * 256 + tid;
                int r = q >> 2, c16 = q & 3;
                int e = r * ASTRIDE + c16 * 8;
                *(uint4*)((char*)dA + e * 2) = pah[i];
            }
        }
        #pragma unroll
        for (int i = 0; i < 2; i++) {
            int q = i * 256 + tid;
            int r = q >> 2, c16 = q & 3;
            int e = r * ASTRIDE + c16 * 8;
            *(uint4*)((char*)dB + e * 2) = pbh[i];
        }
    }
    __syncthreads();

    for (int ch = 0; ch < nch; ch++) {
        const bool more = (ch + 1 < nch);
        // ---- issue global loads for next chunk ----
        if (more) {
            int k0 = (ch + 1) << 5;
            if (F32A) {
                const float* A = (const float*)Aptr;
                #pragma unroll
                for (int i = 0; i < 4; i++) {
                    int q = i * 256 + tid;
                    int r = q >> 3, c4 = q & 7;
                    int gr = row0 + r;
                    pa[i] = (gr < M) ? *(const float4*)(A + (size_t)gr * K + k0 + c4 * 4)
                                     : make_float4(0.f, 0.f, 0.f, 0.f);
                }
            } else {
                const __half* Ah = (const __half*)Aptr;
                #pragma unroll
                for (int i = 0; i < 2; i++) {
                    int q = i * 256 + tid;
                    int r = q >> 2, c16 = q & 3;
                    int gr = row0 + r;
                    pah[i] = (gr < M) ? *(const uint4*)(Ah + (size_t)gr * K + k0 + c16 * 8)
                                      : make_uint4(0, 0, 0, 0);
                }
            }
            #pragma unroll
            for (int i = 0; i < 2; i++) {
                int q = i * 256 + tid;
                int r = q >> 2, c16 = q & 3;
                pbh[i] = *(const uint4*)(Bh + (size_t)r * K + k0 + c16 * 8);
            }
        }

        // ---- compute current stage ----
        const uint32_t uAh = (ch & 1) ? uA1 : uA0;
        const uint32_t uBh = (ch & 1) ? uB1 : uB0;
        #pragma unroll
        for (int ks = 0; ks < 2; ks++) {
            const int kc = ks * 16 + ((lane & 16) ? 8 : 0);
            uint32_t ah[2][4];
            #pragma unroll
            for (int mt = 0; mt < 2; mt++) {
                int r = wm + mt * 16 + (lane & 15);
                uint32_t off = (uint32_t)(r * ASTRIDE + kc) * 2;
                ldsm_x4(ah[mt][0], ah[mt][1], ah[mt][2], ah[mt][3], uAh + off);
            }
            uint32_t bh[8][2];
            const int kcb = ks * 16 + ((lane & 8) ? 8 : 0);
            #pragma unroll
            for (int nt4 = 0; nt4 < 4; nt4++) {
                int n = wn + nt4 * 16 + ((lane & 7) | ((lane & 16) ? 8 : 0));
                uint32_t off = (uint32_t)(n * ASTRIDE + kcb) * 2;
                ldsm_x4(bh[2 * nt4][0], bh[2 * nt4][1], bh[2 * nt4 + 1][0], bh[2 * nt4 + 1][1],
                        uBh + off);
            }
            #pragma unroll
            for (int mt = 0; mt < 2; mt++)
                #pragma unroll
                for (int nt = 0; nt < 8; nt++)
                    mma_f16(c[mt][nt], ah[mt], bh[nt]);
        }

        // ---- store next chunk into the other stage; one barrier per chunk ----
        if (more) {
            __half* dA = sAh[(ch + 1) & 1];
            __half* dB = sBh[(ch + 1) & 1];
            if (F32A) {
                #pragma unroll
                for (int i = 0; i < 4; i++) {
                    int q = i * 256 + tid;
                    int r = q >> 3, c4 = q & 7;
                    float4 v = pa[i];
                    __half2 h0 = __floats2half2_rn(v.x, v.y);
                    __half2 h1 = __floats2half2_rn(v.z, v.w);
                    int e = r * ASTRIDE + c4 * 4;
                    *(uint32_t*)((char*)dA + e * 2)     = *(uint32_t*)&h0;
                    *(uint32_t*)((char*)dA + e * 2 + 4) = *(uint32_t*)&h1;
                }
            } else {
                #pragma unroll
                for (int i = 0; i < 2; i++) {
                    int q = i * 256 + tid;
                    int r = q >> 2, c16 = q & 3;
                    int e = r * ASTRIDE + c16 * 8;
                    *(uint4*)((char*)dA + e * 2) = pah[i];
                }
            }
            #pragma unroll
            for (int i = 0; i < 2; i++) {
                int q = i * 256 + tid;
                int r = q >> 2, c16 = q & 3;
                int e = r * ASTRIDE + c16 * 8;
                *(uint4*)((char*)dB + e * 2) = pbh[i];
            }
            __syncthreads();
        }
    }

    // ---- epilogue: fp16 out ----
    #pragma unroll
    for (int mt = 0; mt < 2; mt++) {
        int gr0 = row0 + wm + mt * 16 + g;
        int gr1 = gr0 + 8;
        #pragma unroll
        for (int nt = 0; nt < 8; nt++) {
            int cc = wn + nt * 8 + 2 * tig;
            if (gr0 < M) *(__half2*)(C + (size_t)gr0 * 128 + cc) = __floats2half2_rn(c[mt][nt][0], c[mt][nt][1]);
            if (gr1 < M) *(__half2*)(C + (size_t)gr1 * 128 + cc) = __floats2half2_rn(c[mt][nt][2], c[mt][nt][3]);
        }
    }
}

__global__ __launch_bounds__(256) void gemm_f32A(const float* __restrict__ A,
                                                 const __half* __restrict__ Bh,
                                                 __half* __restrict__ C, int M, int K) {
    gemm_body<true>(A, Bh, C, M, K);
}
__global__ __launch_bounds__(256) void gemm_f16A(const __half* __restrict__ Ah,
                                                 const __half* __restrict__ Bh,
                                                 __half* __restrict__ C, int M, int K) {
    gemm_body<false>(Ah, Bh, C, M, K);
}

// ---------------- aggregation: one warp per node, CSR gather of fp16 rows ----------------
__device__ __forceinline__ float4 load_row4(const __half* __restrict__ in, int node, int lane) {
    uint2 pv = ((const uint2*)(in + (size_t)node * HIDF))[lane];  // 4 halves
    float2 fa = __half22float2(*(__half2*)&pv.x);
    float2 fb = __half22float2(*(__half2*)&pv.y);
    return make_float4(fa.x, fa.y, fb.x, fb.y);
}

// Layer 1: relu, emit fp16 (feeds gemm_f16A)
__global__ __launch_bounds__(256) void k_agg_f16(const __half* __restrict__ in,
                                                 __half* __restrict__ outh,
                                                 const float* __restrict__ bias) {
    int warp = (blockIdx.x * blockDim.x + threadIdx.x) >> 5;
    int lane = threadIdx.x & 31;
    if (warp >= NN) return;
    float dn = g_dinv[warp];
    float4 v = load_row4(in, warp, lane);
    float s = dn * dn;
    float4 acc = make_float4(v.x * s, v.y * s, v.z * s, v.w * s);
    int beg = g_rowptr[warp], end = g_rowptr[warp + 1];
    for (int j = beg; j < end; j++) {
        int src = g_src[j];
        float w = g_dinv[src] * dn;
        float4 u = load_row4(in, src, lane);
        acc.x += u.x * w; acc.y += u.y * w;
        acc.z += u.z * w; acc.w += u.w * w;
    }
    float4 b = ((const float4*)bias)[lane];
    acc.x = fmaxf(acc.x + b.x, 0.f); acc.y = fmaxf(acc.y + b.y, 0.f);
    acc.z = fmaxf(acc.z + b.z, 0.f); acc.w = fmaxf(acc.w + b.w, 0.f);
    __half2 h0 = __floats2half2_rn(acc.x, acc.y);
    __half2 h1 = __floats2half2_rn(acc.z, acc.w);
    uint2 ph = make_uint2(*(uint32_t*)&h0, *(uint32_t*)&h1);
    ((uint2*)(outh + (size_t)warp * HIDF))[lane] = ph;
}

// Layer 2: fp32 out (final h), no relu
__global__ __launch_bounds__(256) void k_agg_f32(const __half* __restrict__ in,
                                                 float* __restrict__ out,
                                                 const float* __restrict__ bias) {
    int warp = (blockIdx.x * blockDim.x + threadIdx.x) >> 5;
    int lane = threadIdx.x & 31;
    if (warp >= NN) return;
    float dn = g_dinv[warp];
    float4 v = load_row4(in, warp, lane);
    float s = dn * dn;
    float4 acc = make_float4(v.x * s, v.y * s, v.z * s, v.w * s);
    int beg = g_rowptr[warp], end = g_rowptr[warp + 1];
    for (int j = beg; j < end; j++) {
        int src = g_src[j];
        float w = g_dinv[src] * dn;
        float4 u = load_row4(in, src, lane);
        acc.x += u.x * w; acc.y += u.y * w;
        acc.z += u.z * w; acc.w += u.w * w;
    }
    float4 b = ((const float4*)bias)[lane];
    acc.x += b.x; acc.y += b.y; acc.z += b.z; acc.w += b.w;
    ((float4*)(out + (size_t)warp * HIDF))[lane] = acc;
}

// ---------------- global_add_pool: batch is sorted -> segmented sum ----------------
__global__ void k_pool(const float* __restrict__ h, const int* __restrict__ batch,
                       float* __restrict__ out) {
    int g = blockIdx.x;
    int t = threadIdx.x;
    int a = 0, b = NN;
    while (a < b) { int m = (a + b) >> 1; if (batch[m] < g) a = m + 1; else b = m; }
    int s = a;
    a = 0; b = NN;
    while (a < b) { int m = (a + b) >> 1; if (batch[m] < g + 1) a = m + 1; else b = m; }
    int e = a;
    float acc = 0.f;
    for (int n = s; n < e; n++) acc += h[(size_t)n * HIDF + t];
    out[(size_t)g * HIDF + t] = acc;
}

// ---------------- launch ----------------
extern "C" void kernel_launch(void* const* d_in, const int* in_sizes, int n_in,
                              void* d_out, int out_size) {
    const float* x     = (const float*)d_in[0];
    const float* W1    = (const float*)d_in[1];
    const float* b1    = (const float*)d_in[2];
    const float* W2    = (const float*)d_in[3];
    const float* b2    = (const float*)d_in[4];
    const int*   ei    = (const int*)d_in[5];
    const int*   batch = (const int*)d_in[6];
    const int* row = ei;        // edge_index[0] = source
    const int* col = ei + NE;   // edge_index[1] = target

    float* out_hs = (float*)d_out;
    float* out_h  = (float*)d_out + (size_t)NG * HIDF;

    __half *g1, *h1h, *w1h, *w2h;
    cudaGetSymbolAddress((void**)&g1, g_g1);
    cudaGetSymbolAddress((void**)&h1h, g_h1h);
    cudaGetSymbolAddress((void**)&w1h, g_w1h);
    cudaGetSymbolAddress((void**)&w2h, g_w2h);

    cudaFuncSetAttribute(k_scan, cudaFuncAttributeMaxDynamicSharedMemorySize, NN * 4);

    // fork-join streams (created per call; see round-10 note on lifetime)
    cudaStream_t s2;
    cudaStreamCreateWithFlags(&s2, cudaStreamNonBlocking);
    cudaEvent_t evFork, evJoin;
    cudaEventCreateWithFlags(&evFork, cudaEventDisableTiming);
    cudaEventCreateWithFlags(&evJoin, cudaEventDisableTiming);

    cudaEventRecord(evFork, 0);
    cudaStreamWaitEvent(s2, evFork, 0);

    // branch B (s2): CSR build
    k_count<<<(NE / 2 + 255) / 256, 256, 0, s2>>>(col);
    k_scan<<<1, 1024, NN * 4, s2>>>();
    k_fill<<<(NE / 2 + 255) / 256, 256, 0, s2>>>(row, col);
    cudaEventRecord(evJoin, s2);

    const int GEMM_GRID = (NN + 127) / 128;  // 391
    const int AGG_GRID  = (NN + 7) / 8;      // 6250

    // branch A (origin): weights + layer-1 GEMM
    k_prepw<<<256, 256>>>(W1, W2);
    gemm_f32A<<<GEMM_GRID, 256>>>(x, w1h, g1, NN, INF_);

    // join: aggregation needs CSR
    cudaStreamWaitEvent(0, evJoin, 0);
    k_agg_f16<<<AGG_GRID, 256>>>(g1, h1h, b1);

    // layer 2
    gemm_f16A<<<GEMM_GRID, 256>>>(h1h, w2h, g1, NN, HIDF);
    k_agg_f32<<<AGG_GRID, 256>>>(g1, out_h, b2);

    // pooling
    k_pool<<<NG, 128>>>(out_h, batch, out_hs);
}

// round 16
// speedup vs baseline: 1.0040x; 1.0040x over previous
#include <cuda_runtime.h>
#include <cuda_fp16.h>
#include <cstdint>
#include <cstddef>

#define NN   50000
#define NE   640000
#define INF_ 512
#define HIDF 128
#define NG   256

// ---------------- device scratch (no allocations allowed) ----------------
__device__ int   g_cnt[NN];          // zero at load; k_scan restores to zero each launch
__device__ float g_dinv[NN];
__device__ int   g_rowptr[NN + 1];
__device__ int   g_rank[NE];
__device__ int   g_src[NE];
__device__ __half g_g1[(size_t)NN * HIDF];    // layer-1 gemm output (fp16)
__device__ __half g_h1h[(size_t)NN * HIDF];   // fused agg1+gemm2 output (fp16)
// transposed fp16 weights: Wt[n][k] = W[k][n]
__device__ __half g_w1h[128 * 512];
__device__ __half g_w2h[128 * 128];

// ---------------- helpers ----------------
__device__ __forceinline__ uint32_t smem_u32(const void* p) {
    uint32_t a;
    asm("{ .reg .u64 t; cvta.to.shared.u64 t, %1; cvt.u32.u64 %0, t; }" : "=r"(a) : "l"(p));
    return a;
}
__device__ __forceinline__ void ldsm_x4(uint32_t& r0, uint32_t& r1, uint32_t& r2, uint32_t& r3,
                                        uint32_t addr) {
    asm volatile("ldmatrix.sync.aligned.m8n8.x4.shared.b16 {%0,%1,%2,%3}, [%4];"
                 : "=r"(r0), "=r"(r1), "=r"(r2), "=r"(r3) : "r"(addr));
}
__device__ __forceinline__ void mma_f16(float* c, const uint32_t* a, const uint32_t* b) {
    asm volatile(
        "mma.sync.aligned.m16n8k16.row.col.f32.f16.f16.f32 "
        "{%0,%1,%2,%3}, {%4,%5,%6,%7}, {%8,%9}, {%0,%1,%2,%3};"
        : "+f"(c[0]), "+f"(c[1]), "+f"(c[2]), "+f"(c[3])
        : "r"(a[0]), "r"(a[1]), "r"(a[2]), "r"(a[3]), "r"(b[0]), "r"(b[1]));
}

// ---------------- preprocessing ----------------
// transpose/cast weights; consecutive threads read consecutive W elements
__global__ void k_prepw(const float* __restrict__ W1, const float* __restrict__ W2) {
    int i = blockIdx.x * blockDim.x + threadIdx.x;
    if (i < 128 * 512) {
        int k = i >> 7, n = i & 127;
        g_w1h[n * 512 + k] = __float2half_rn(W1[i]);
    }
    if (i < 128 * 128) {
        int k = i >> 7, n = i & 127;
        g_w2h[n * 128 + k] = __float2half_rn(W2[i]);
    }
}

// count + record per-edge rank within destination (atomicAdd return value), 2 edges/thread
__global__ void k_count(const int* __restrict__ col) {
    int t = blockIdx.x * blockDim.x + threadIdx.x;
    if (t < NE / 2) {
        int2 c2 = ((const int2*)col)[t];
        int2 r;
        r.x = atomicAdd(&g_cnt[c2.x], 1);
        r.y = atomicAdd(&g_cnt[c2.y], 1);
        ((int2*)g_rank)[t] = r;
    }
}

// single-block scan, smem-staged for fully coalesced global access.
// Also restores g_cnt to zero for the next launch (invariant: zero at entry).
__global__ __launch_bounds__(1024) void k_scan() {
    extern __shared__ int sc[];   // NN ints = 200 000 B
    __shared__ int wsum[32];
    int t = threadIdx.x, lane = t & 31, w = t >> 5;
    for (int i = t; i < NN; i += 1024) {
        int c = g_cnt[i];
        sc[i] = c;
        g_dinv[i] = rsqrtf((float)(c + 1));  // +1 self-loop
        g_cnt[i] = 0;                        // restore invariant for next launch
    }
    __syncthreads();
    const int SEG = (NN + 1023) / 1024;  // 49
    int s0 = t * SEG, s1 = s0 + SEG;
    if (s1 > NN) s1 = NN;
    if (s0 > NN) s0 = NN;
    int s = 0;
    for (int i = s0; i < s1; i++) s += sc[i];
    int v = s;
    #pragma unroll
    for (int o = 1; o < 32; o <<= 1) {
        int u = __shfl_up_sync(0xFFFFFFFFu, v, o);
        if (lane >= o) v += u;
    }
    if (lane == 31) wsum[w] = v;
    __syncthreads();
    if (w == 0) {
        int x = wsum[lane];
        #pragma unroll
        for (int o = 1; o < 32; o <<= 1) {
            int u = __shfl_up_sync(0xFFFFFFFFu, x, o);
            if (lane >= o) x += u;
        }
        wsum[lane] = x;
    }
    __syncthreads();
    int P = v - s + (w > 0 ? wsum[w - 1] : 0);
    for (int i = s0; i < s1; i++) {
        int c = sc[i];
        sc[i] = P;     // in-place exclusive prefix
        P += c;
    }
    __syncthreads();
    for (int i = t; i < NN; i += 1024) g_rowptr[i] = sc[i];
    if (t == 0) g_rowptr[NN] = wsum[31];
}

// atomic-free fill using precomputed ranks, 2 edges/thread
__global__ void k_fill(const int* __restrict__ row, const int* __restrict__ col) {
    int t = blockIdx.x * blockDim.x + threadIdx.x;
    if (t < NE / 2) {
        int2 r2 = ((const int2*)row)[t];
        int2 c2 = ((const int2*)col)[t];
        int2 k2 = ((const int2*)g_rank)[t];
        g_src[g_rowptr[c2.x] + k2.x] = r2.x;
        g_src[g_rowptr[c2.y] + k2.y] = r2.y;
    }
}

// ---------------- GEMM1 (HMMA): C[M,128] = fp16(A[M,512]) @ W1t^T, fp16 out ----------------
// Single-buffer smem (round-13 anchor form).
#define ASTRIDE 40  // fp16 elems per smem row (80 B), conflict-free ldmatrix

__global__ __launch_bounds__(256) void gemm_f32A(const float* __restrict__ A,
                                                 const __half* __restrict__ Bh,
                                                 __half* __restrict__ C, int M, int K) {
    __shared__ __half sAh[128 * ASTRIDE];
    __shared__ __half sBh[128 * ASTRIDE];
    const int tid = threadIdx.x;
    const int wid = tid >> 5, lane = tid & 31;
    const int wm = (wid >> 1) * 32;
    const int wn = (wid & 1) * 64;
    const int g = lane >> 2, tig = lane & 3;
    const int row0 = blockIdx.x * 128;

    const uint32_t uAh = smem_u32(sAh);
    const uint32_t uBh = smem_u32(sBh);

    float c[2][8][4];
    #pragma unroll
    for (int mt = 0; mt < 2; mt++)
        #pragma unroll
        for (int nt = 0; nt < 8; nt++)
            #pragma unroll
            for (int q = 0; q < 4; q++) c[mt][nt][q] = 0.f;

    const int nch = K >> 5;

    float4 pa[4];
    uint4 pbh[2];

    #pragma unroll
    for (int i = 0; i < 4; i++) {
        int q = i * 256 + tid;
        int r = q >> 3, c4 = q & 7;
        int gr = row0 + r;
        pa[i] = (gr < M) ? *(const float4*)(A + (size_t)gr * K + c4 * 4)
                         : make_float4(0.f, 0.f, 0.f, 0.f);
    }
    #pragma unroll
    for (int i = 0; i < 2; i++) {
        int q = i * 256 + tid;
        int r = q >> 2, c16 = q & 3;
        pbh[i] = *(const uint4*)(Bh + (size_t)r * K + c16 * 8);
    }

    for (int ch = 0; ch < nch; ch++) {
        #pragma unroll
        for (int i = 0; i < 4; i++) {
            int q = i * 256 + tid;
            int r = q >> 3, c4 = q & 7;
            float4 v = pa[i];
            __half2 h0 = __floats2half2_rn(v.x, v.y);
            __half2 h1 = __floats2half2_rn(v.z, v.w);
            int e = r * ASTRIDE + c4 * 4;
            *(uint32_t*)((char*)sAh + e * 2)     = *(uint32_t*)&h0;
            *(uint32_t*)((char*)sAh + e * 2 + 4) = *(uint32_t*)&h1;
        }
        #pragma unroll
        for (int i = 0; i < 2; i++) {
            int q = i * 256 + tid;
            int r = q >> 2, c16 = q & 3;
            int e = r * ASTRIDE + c16 * 8;
            *(uint4*)((char*)sBh + e * 2) = pbh[i];
        }
        __syncthreads();

        if (ch + 1 < nch) {
            int k0 = (ch + 1) << 5;
            #pragma unroll
            for (int i = 0; i < 4; i++) {
                int q = i * 256 + tid;
                int r = q >> 3, c4 = q & 7;
                int gr = row0 + r;
                pa[i] = (gr < M) ? *(const float4*)(A + (size_t)gr * K + k0 + c4 * 4)
                                 : make_float4(0.f, 0.f, 0.f, 0.f);
            }
            #pragma unroll
            for (int i = 0; i < 2; i++) {
                int q = i * 256 + tid;
                int r = q >> 2, c16 = q & 3;
                pbh[i] = *(const uint4*)(Bh + (size_t)r * K + k0 + c16 * 8);
            }
        }

        #pragma unroll
        for (int ks = 0; ks < 2; ks++) {
            const int kc = ks * 16 + ((lane & 16) ? 8 : 0);
            uint32_t ah[2][4];
            #pragma unroll
            for (int mt = 0; mt < 2; mt++) {
                int r = wm + mt * 16 + (lane & 15);
                uint32_t off = (uint32_t)(r * ASTRIDE + kc) * 2;
                ldsm_x4(ah[mt][0], ah[mt][1], ah[mt][2], ah[mt][3], uAh + off);
            }
            uint32_t bh[8][2];
            const int kcb = ks * 16 + ((lane & 8) ? 8 : 0);
            #pragma unroll
            for (int nt4 = 0; nt4 < 4; nt4++) {
                int n = wn + nt4 * 16 + ((lane & 7) | ((lane & 16) ? 8 : 0));
                uint32_t off = (uint32_t)(n * ASTRIDE + kcb) * 2;
                ldsm_x4(bh[2 * nt4][0], bh[2 * nt4][1], bh[2 * nt4 + 1][0], bh[2 * nt4 + 1][1],
                        uBh + off);
            }
            #pragma unroll
            for (int mt = 0; mt < 2; mt++)
                #pragma unroll
                for (int nt = 0; nt < 8; nt++)
                    mma_f16(c[mt][nt], ah[mt], bh[nt]);
        }
        __syncthreads();
    }

    #pragma unroll
    for (int mt = 0; mt < 2; mt++) {
        int gr0 = row0 + wm + mt * 16 + g;
        int gr1 = gr0 + 8;
        #pragma unroll
        for (int nt = 0; nt < 8; nt++) {
            int cc = wn + nt * 8 + 2 * tig;
            if (gr0 < M) *(__half2*)(C + (size_t)gr0 * 128 + cc) = __floats2half2_rn(c[mt][nt][0], c[mt][nt][1]);
            if (gr1 < M) *(__half2*)(C + (size_t)gr1 * 128 + cc) = __floats2half2_rn(c[mt][nt][2], c[mt][nt][3]);
        }
    }
}

// ---------------- row gather helper ----------------
__device__ __forceinline__ float4 load_row4(const __half* __restrict__ in, int node, int lane) {
    uint2 pv = ((const uint2*)(in + (size_t)node * HIDF))[lane];  // 4 halves
    float2 fa = __half22float2(*(__half2*)&pv.x);
    float2 fb = __half22float2(*(__half2*)&pv.y);
    return make_float4(fa.x, fa.y, fb.x, fb.y);
}

// ---------------- FUSED agg1 + GEMM2 ----------------
// CTA b: aggregate nodes [128b,128b+128) from g1 (+relu+b1) directly into smem
// A-tiles, then MMA against W2 (smem) -> h1h. No grid sync needed: C row m
// depends only on h1 row m. 512 threads, warp tile 32x32, 4 K-chunks.
#define CHB (128 * ASTRIDE * 2)            // bytes per chunk buffer = 10240
#define FUSED_SMEM (8 * CHB)               // 4 A-chunks + 4 B-chunks = 81920

__global__ __launch_bounds__(512, 2) void k_fused(const __half* __restrict__ in,
                                                  const __half* __restrict__ Bh,
                                                  __half* __restrict__ Cout,
                                                  const float* __restrict__ bias) {
    extern __shared__ char sm[];
    char* sA = sm;
    char* sB = sm + 4 * CHB;
    const int tid = threadIdx.x;
    const int wid = tid >> 5, lane = tid & 31;
    const int row0 = blockIdx.x * 128;

    // phase 0: load B = w2h [n][k] into 4 chunk buffers (k-chunks of 32)
    #pragma unroll
    for (int i = 0; i < 4; i++) {
        int q = i * 512 + tid;            // 0..2047 uint4 units
        int n = q >> 4, seg = q & 15;
        int k = seg * 8;
        int chunk = k >> 5, kin = k & 31;
        *(uint4*)(sB + chunk * CHB + (n * ASTRIDE + kin) * 2) =
            *(const uint4*)(Bh + n * 128 + k);
    }

    // phase 1: aggregate 8 nodes per warp, write rows into A chunk buffers
    const int chA = lane >> 3;            // K-chunk for this lane's 4 cols
    const int kinA = (4 * lane) & 31;
    #pragma unroll 1
    for (int i = 0; i < 8; i++) {
        int r = wid + i * 16;             // 0..127
        int node = row0 + r;
        float4 acc = make_float4(0.f, 0.f, 0.f, 0.f);
        if (node < NN) {
            float dn = g_dinv[node];
            float4 v = load_row4(in, node, lane);
            float s = dn * dn;
            acc = make_float4(v.x * s, v.y * s, v.z * s, v.w * s);
            int beg = g_rowptr[node], end = g_rowptr[node + 1];
            for (int j = beg; j < end; j++) {
                int src = g_src[j];
                float wgt = g_dinv[src] * dn;
                float4 u = load_row4(in, src, lane);
                acc.x += u.x * wgt; acc.y += u.y * wgt;
                acc.z += u.z * wgt; acc.w += u.w * wgt;
            }
            float4 b = ((const float4*)bias)[lane];
            acc.x = fmaxf(acc.x + b.x, 0.f); acc.y = fmaxf(acc.y + b.y, 0.f);
            acc.z = fmaxf(acc.z + b.z, 0.f); acc.w = fmaxf(acc.w + b.w, 0.f);
        }
        __half2 h0 = __floats2half2_rn(acc.x, acc.y);
        __half2 h1 = __floats2half2_rn(acc.z, acc.w);
        char* dst = sA + chA * CHB + (r * ASTRIDE + kinA) * 2;
        *(uint32_t*)dst       = *(uint32_t*)&h0;
        *(uint32_t*)(dst + 4) = *(uint32_t*)&h1;
    }
    __syncthreads();

    // phase 2: MMA 128x128x128, warp tile 32x32 (16 warps)
    const int wm = (wid >> 2) * 32;
    const int wn = (wid & 3) * 32;
    const int g = lane >> 2, tig = lane & 3;
    float c[2][4][4];
    #pragma unroll
    for (int mt = 0; mt < 2; mt++)
        #pragma unroll
        for (int nt = 0; nt < 4; nt++)
            #pragma unroll
            for (int q = 0; q < 4; q++) c[mt][nt][q] = 0.f;

    #pragma unroll
    for (int ch = 0; ch < 4; ch++) {
        const uint32_t uA = smem_u32(sA + ch * CHB);
        const uint32_t uB = smem_u32(sB + ch * CHB);
        #pragma unroll
        for (int ks = 0; ks < 2; ks++) {
            const int kc = ks * 16 + ((lane & 16) ? 8 : 0);
            uint32_t ah[2][4];
            #pragma unroll
            for (int mt = 0; mt < 2; mt++) {
                int r = wm + mt * 16 + (lane & 15);
                ldsm_x4(ah[mt][0], ah[mt][1], ah[mt][2], ah[mt][3],
                        uA + (uint32_t)(r * ASTRIDE + kc) * 2);
            }
            uint32_t bh[4][2];
            const int kcb = ks * 16 + ((lane & 8) ? 8 : 0);
            #pragma unroll
            for (int nt4 = 0; nt4 < 2; nt4++) {
                int n = wn + nt4 * 16 + ((lane & 7) | ((lane & 16) ? 8 : 0));
                ldsm_x4(bh[2 * nt4][0], bh[2 * nt4][1], bh[2 * nt4 + 1][0], bh[2 * nt4 + 1][1],
                        uB + (uint32_t)(n * ASTRIDE + kcb) * 2);
            }
            #pragma unroll
            for (int mt = 0; mt < 2; mt++)
                #pragma unroll
                for (int nt = 0; nt < 4; nt++)
                    mma_f16(c[mt][nt], ah[mt], bh[nt]);
        }
    }

    // epilogue: fp16 out
    #pragma unroll
    for (int mt = 0; mt < 2; mt++) {
        int gr0 = row0 + wm + mt * 16 + g;
        int gr1 = gr0 + 8;
        #pragma unroll
        for (int nt = 0; nt < 4; nt++) {
            int cc = wn + nt * 8 + 2 * tig;
            if (gr0 < NN) *(__half2*)(Cout + (size_t)gr0 * 128 + cc) = __floats2half2_rn(c[mt][nt][0], c[mt][nt][1]);
            if (gr1 < NN) *(__half2*)(Cout + (size_t)gr1 * 128 + cc) = __floats2half2_rn(c[mt][nt][2], c[mt][nt][3]);
        }
    }
}

// ---------------- layer-2 aggregation: fp32 out (final h), no relu ----------------
__global__ __launch_bounds__(256) void k_agg_f32(const __half* __restrict__ in,
                                                 float* __restrict__ out,
                                                 const float* __restrict__ bias) {
    int warp = (blockIdx.x * blockDim.x + threadIdx.x) >> 5;
    int lane = threadIdx.x & 31;
    if (warp >= NN) return;
    float dn = g_dinv[warp];
    float4 v = load_row4(in, warp, lane);
    float s = dn * dn;
    float4 acc = make_float4(v.x * s, v.y * s, v.z * s, v.w * s);
    int beg = g_rowptr[warp], end = g_rowptr[warp + 1];
    for (int j = beg; j < end; j++) {
        int src = g_src[j];
        float w = g_dinv[src] * dn;
        float4 u = load_row4(in, src, lane);
        acc.x += u.x * w; acc.y += u.y * w;
        acc.z += u.z * w; acc.w += u.w * w;
    }
    float4 b = ((const float4*)bias)[lane];
    acc.x += b.x; acc.y += b.y; acc.z += b.z; acc.w += b.w;
    ((float4*)(out + (size_t)warp * HIDF))[lane] = acc;
}

// ---------------- global_add_pool: batch is sorted -> segmented sum ----------------
__global__ void k_pool(const float* __restrict__ h, const int* __restrict__ batch,
                       float* __restrict__ out) {
    int g = blockIdx.x;
    int t = threadIdx.x;
    int a = 0, b = NN;
    while (a < b) { int m = (a + b) >> 1; if (batch[m] < g) a = m + 1; else b = m; }
    int s = a;
    a = 0; b = NN;
    while (a < b) { int m = (a + b) >> 1; if (batch[m] < g + 1) a = m + 1; else b = m; }
    int e = a;
    float acc = 0.f;
    for (int n = s; n < e; n++) acc += h[(size_t)n * HIDF + t];
    out[(size_t)g * HIDF + t] = acc;
}

// ---------------- launch ----------------
extern "C" void kernel_launch(void* const* d_in, const int* in_sizes, int n_in,
                              void* d_out, int out_size) {
    const float* x     = (const float*)d_in[0];
    const float* W1    = (const float*)d_in[1];
    const float* b1    = (const float*)d_in[2];
    const float* W2    = (const float*)d_in[3];
    const float* b2    = (const float*)d_in[4];
    const int*   ei    = (const int*)d_in[5];
    const int*   batch = (const int*)d_in[6];
    const int* row = ei;        // edge_index[0] = source
    const int* col = ei + NE;   // edge_index[1] = target

    float* out_hs = (float*)d_out;
    float* out_h  = (float*)d_out + (size_t)NG * HIDF;

    __half *g1, *h1h, *w1h, *w2h;
    cudaGetSymbolAddress((void**)&g1, g_g1);
    cudaGetSymbolAddress((void**)&h1h, g_h1h);
    cudaGetSymbolAddress((void**)&w1h, g_w1h);
    cudaGetSymbolAddress((void**)&w2h, g_w2h);

    cudaFuncSetAttribute(k_scan, cudaFuncAttributeMaxDynamicSharedMemorySize, NN * 4);
    cudaFuncSetAttribute(k_fused, cudaFuncAttributeMaxDynamicSharedMemorySize, FUSED_SMEM);

    // fork-join streams (created per call; see round-10 note on lifetime)
    cudaStream_t s2;
    cudaStreamCreateWithFlags(&s2, cudaStreamNonBlocking);
    cudaEvent_t evFork, evJoin;
    cudaEventCreateWithFlags(&evFork, cudaEventDisableTiming);
    cudaEventCreateWithFlags(&evJoin, cudaEventDisableTiming);

    cudaEventRecord(evFork, 0);
    cudaStreamWaitEvent(s2, evFork, 0);

    // branch B (s2): CSR build
    k_count<<<(NE / 2 + 255) / 256, 256, 0, s2>>>(col);
    k_scan<<<1, 1024, NN * 4, s2>>>();
    k_fill<<<(NE / 2 + 255) / 256, 256, 0, s2>>>(row, col);
    cudaEventRecord(evJoin, s2);

    const int GEMM_GRID = (NN + 127) / 128;  // 391
    const int AGG_GRID  = (NN + 7) / 8;      // 6250

    // branch A (origin): weights + layer-1 GEMM
    k_prepw<<<256, 256>>>(W1, W2);
    gemm_f32A<<<GEMM_GRID, 256>>>(x, w1h, g1, NN, INF_);

    // join: aggregation needs CSR
    cudaStreamWaitEvent(0, evJoin, 0);

    // fused agg1 + gemm2
    k_fused<<<GEMM_GRID, 512, FUSED_SMEM>>>(g1, w2h, h1h, b1);

    // layer-2 aggregation + pooling
    k_agg_f32<<<AGG_GRID, 256>>>(h1h, out_h, b2);
    k_pool<<<NG, 128>>>(out_h, batch, out_hs);
}

// round 17
// speedup vs baseline: 1.1186x; 1.1141x over previous
#include <cuda_runtime.h>
#include <cuda_fp16.h>
#include <cstdint>
#include <cstddef>

#define NN   50000
#define NE   640000
#define INF_ 512
#define HIDF 128
#define NG   256

// ---------------- device scratch (no allocations allowed) ----------------
__device__ int   g_cnt[NN];          // zero at load; k_scan restores to zero each launch
__device__ float g_dinv[NN];
__device__ int   g_rowptr[NN + 1];
__device__ int   g_rank[NE];
__device__ int   g_src[NE];
__device__ __half g_g1[(size_t)NN * HIDF];    // gemm outputs (fp16), reused both layers
__device__ __half g_h1h[(size_t)NN * HIDF];   // layer-1 agg output (fp16)
// transposed fp16 weights: Wt[n][k] = W[k][n]
__device__ __half g_w1h[128 * 512];
__device__ __half g_w2h[128 * 128];

// ---------------- helpers ----------------
__device__ __forceinline__ uint32_t smem_u32(const void* p) {
    uint32_t a;
    asm("{ .reg .u64 t; cvta.to.shared.u64 t, %1; cvt.u32.u64 %0, t; }" : "=r"(a) : "l"(p));
    return a;
}
__device__ __forceinline__ void ldsm_x4(uint32_t& r0, uint32_t& r1, uint32_t& r2, uint32_t& r3,
                                        uint32_t addr) {
    asm volatile("ldmatrix.sync.aligned.m8n8.x4.shared.b16 {%0,%1,%2,%3}, [%4];"
                 : "=r"(r0), "=r"(r1), "=r"(r2), "=r"(r3) : "r"(addr));
}
__device__ __forceinline__ void mma_f16(float* c, const uint32_t* a, const uint32_t* b) {
    asm volatile(
        "mma.sync.aligned.m16n8k16.row.col.f32.f16.f16.f32 "
        "{%0,%1,%2,%3}, {%4,%5,%6,%7}, {%8,%9}, {%0,%1,%2,%3};"
        : "+f"(c[0]), "+f"(c[1]), "+f"(c[2]), "+f"(c[3])
        : "r"(a[0]), "r"(a[1]), "r"(a[2]), "r"(a[3]), "r"(b[0]), "r"(b[1]));
}

// ---------------- preprocessing ----------------
// transpose/cast weights; consecutive threads read consecutive W elements
__global__ void k_prepw(const float* __restrict__ W1, const float* __restrict__ W2) {
    int i = blockIdx.x * blockDim.x + threadIdx.x;
    if (i < 128 * 512) {
        int k = i >> 7, n = i & 127;
        g_w1h[n * 512 + k] = __float2half_rn(W1[i]);
    }
    if (i < 128 * 128) {
        int k = i >> 7, n = i & 127;
        g_w2h[n * 128 + k] = __float2half_rn(W2[i]);
    }
}

// count + record per-edge rank within destination (atomicAdd return value), 2 edges/thread
__global__ void k_count(const int* __restrict__ col) {
    int t = blockIdx.x * blockDim.x + threadIdx.x;
    if (t < NE / 2) {
        int2 c2 = ((const int2*)col)[t];
        int2 r;
        r.x = atomicAdd(&g_cnt[c2.x], 1);
        r.y = atomicAdd(&g_cnt[c2.y], 1);
        ((int2*)g_rank)[t] = r;
    }
}

// single-block scan, smem-staged for fully coalesced global access.
// Also restores g_cnt to zero for the next launch, and zero-inits out_hs
// (d_out is poisoned 0xAA; the fused agg2+pool accumulates via atomics).
__global__ __launch_bounds__(1024) void k_scan(float* __restrict__ out_hs) {
    extern __shared__ int sc[];   // NN ints = 200 000 B
    __shared__ int wsum[32];
    int t = threadIdx.x, lane = t & 31, w = t >> 5;
    for (int i = t; i < NG * HIDF; i += 1024) out_hs[i] = 0.f;
    for (int i = t; i < NN; i += 1024) {
        int c = g_cnt[i];
        sc[i] = c;
        g_dinv[i] = rsqrtf((float)(c + 1));  // +1 self-loop
        g_cnt[i] = 0;                        // restore invariant for next launch
    }
    __syncthreads();
    const int SEG = (NN + 1023) / 1024;  // 49
    int s0 = t * SEG, s1 = s0 + SEG;
    if (s1 > NN) s1 = NN;
    if (s0 > NN) s0 = NN;
    int s = 0;
    for (int i = s0; i < s1; i++) s += sc[i];
    int v = s;
    #pragma unroll
    for (int o = 1; o < 32; o <<= 1) {
        int u = __shfl_up_sync(0xFFFFFFFFu, v, o);
        if (lane >= o) v += u;
    }
    if (lane == 31) wsum[w] = v;
    __syncthreads();
    if (w == 0) {
        int x = wsum[lane];
        #pragma unroll
        for (int o = 1; o < 32; o <<= 1) {
            int u = __shfl_up_sync(0xFFFFFFFFu, x, o);
            if (lane >= o) x += u;
        }
        wsum[lane] = x;
    }
    __syncthreads();
    int P = v - s + (w > 0 ? wsum[w - 1] : 0);
    for (int i = s0; i < s1; i++) {
        int c = sc[i];
        sc[i] = P;     // in-place exclusive prefix
        P += c;
    }
    __syncthreads();
    for (int i = t; i < NN; i += 1024) g_rowptr[i] = sc[i];
    if (t == 0) g_rowptr[NN] = wsum[31];
}

// atomic-free fill using precomputed ranks, 2 edges/thread
__global__ void k_fill(const int* __restrict__ row, const int* __restrict__ col) {
    int t = blockIdx.x * blockDim.x + threadIdx.x;
    if (t < NE / 2) {
        int2 r2 = ((const int2*)row)[t];
        int2 c2 = ((const int2*)col)[t];
        int2 k2 = ((const int2*)g_rank)[t];
        g_src[g_rowptr[c2.x] + k2.x] = r2.x;
        g_src[g_rowptr[c2.y] + k2.y] = r2.y;
    }
}

// ---------------- HMMA GEMM: C[M,128] = A[M,K] @ Wt^T, fp16 out ----------------
#define ASTRIDE 40  // fp16 elems per smem row (80 B), conflict-free ldmatrix

template <bool F32A>
__device__ __forceinline__ void gemm_body(const void* __restrict__ Aptr,
                                          const __half* __restrict__ Bh,
                                          __half* __restrict__ C,
                                          int M, int K) {
    __shared__ __half sAh[128 * ASTRIDE];
    __shared__ __half sBh[128 * ASTRIDE];
    const int tid = threadIdx.x;
    const int wid = tid >> 5, lane = tid & 31;
    const int wm = (wid >> 1) * 32;
    const int wn = (wid & 1) * 64;
    const int g = lane >> 2, tig = lane & 3;
    const int row0 = blockIdx.x * 128;

    const uint32_t uAh = smem_u32(sAh);
    const uint32_t uBh = smem_u32(sBh);

    float c[2][8][4];
    #pragma unroll
    for (int mt = 0; mt < 2; mt++)
        #pragma unroll
        for (int nt = 0; nt < 8; nt++)
            #pragma unroll
            for (int q = 0; q < 4; q++) c[mt][nt][q] = 0.f;

    const int nch = K >> 5;

    float4 pa[4];
    uint4 pah[2];
    uint4 pbh[2];

    if (F32A) {
        const float* A = (const float*)Aptr;
        #pragma unroll
        for (int i = 0; i < 4; i++) {
            int q = i * 256 + tid;
            int r = q >> 3, c4 = q & 7;
            int gr = row0 + r;
            pa[i] = (gr < M) ? *(const float4*)(A + (size_t)gr * K + c4 * 4)
                             : make_float4(0.f, 0.f, 0.f, 0.f);
        }
    } else {
        const __half* Ah = (const __half*)Aptr;
        #pragma unroll
        for (int i = 0; i < 2; i++) {
            int q = i * 256 + tid;
            int r = q >> 2, c16 = q & 3;
            int gr = row0 + r;
            pah[i] = (gr < M) ? *(const uint4*)(Ah + (size_t)gr * K + c16 * 8)
                              : make_uint4(0, 0, 0, 0);
        }
    }
    #pragma unroll
    for (int i = 0; i < 2; i++) {
        int q = i * 256 + tid;
        int r = q >> 2, c16 = q & 3;
        pbh[i] = *(const uint4*)(Bh + (size_t)r * K + c16 * 8);
    }

    for (int ch = 0; ch < nch; ch++) {
        if (F32A) {
            #pragma unroll
            for (int i = 0; i < 4; i++) {
                int q = i * 256 + tid;
                int r = q >> 3, c4 = q & 7;
                float4 v = pa[i];
                __half2 h0 = __floats2half2_rn(v.x, v.y);
                __half2 h1 = __floats2half2_rn(v.z, v.w);
                int e = r * ASTRIDE + c4 * 4;
                *(uint32_t*)((char*)sAh + e * 2)     = *(uint32_t*)&h0;
                *(uint32_t*)((char*)sAh + e * 2 + 4) = *(uint32_t*)&h1;
            }
        } else {
            #pragma unroll
            for (int i = 0; i < 2; i++) {
                int q = i * 256 + tid;
                int r = q >> 2, c16 = q & 3;
                int e = r * ASTRIDE + c16 * 8;
                *(uint4*)((char*)sAh + e * 2) = pah[i];
            }
        }
        #pragma unroll
        for (int i = 0; i < 2; i++) {
            int q = i * 256 + tid;
            int r = q >> 2, c16 = q & 3;
            int e = r * ASTRIDE + c16 * 8;
            *(uint4*)((char*)sBh + e * 2) = pbh[i];
        }
        __syncthreads();

        if (ch + 1 < nch) {
            int k0 = (ch + 1) << 5;
            if (F32A) {
                const float* A = (const float*)Aptr;
                #pragma unroll
                for (int i = 0; i < 4; i++) {
                    int q = i * 256 + tid;
                    int r = q >> 3, c4 = q & 7;
                    int gr = row0 + r;
                    pa[i] = (gr < M) ? *(const float4*)(A + (size_t)gr * K + k0 + c4 * 4)
                                     : make_float4(0.f, 0.f, 0.f, 0.f);
                }
            } else {
                const __half* Ah = (const __half*)Aptr;
                #pragma unroll
                for (int i = 0; i < 2; i++) {
                    int q = i * 256 + tid;
                    int r = q >> 2, c16 = q & 3;
                    int gr = row0 + r;
                    pah[i] = (gr < M) ? *(const uint4*)(Ah + (size_t)gr * K + k0 + c16 * 8)
                                      : make_uint4(0, 0, 0, 0);
                }
            }
            #pragma unroll
            for (int i = 0; i < 2; i++) {
                int q = i * 256 + tid;
                int r = q >> 2, c16 = q & 3;
                pbh[i] = *(const uint4*)(Bh + (size_t)r * K + k0 + c16 * 8);
            }
        }

        #pragma unroll
        for (int ks = 0; ks < 2; ks++) {
            const int kc = ks * 16 + ((lane & 16) ? 8 : 0);
            uint32_t ah[2][4];
            #pragma unroll
            for (int mt = 0; mt < 2; mt++) {
                int r = wm + mt * 16 + (lane & 15);
                uint32_t off = (uint32_t)(r * ASTRIDE + kc) * 2;
                ldsm_x4(ah[mt][0], ah[mt][1], ah[mt][2], ah[mt][3], uAh + off);
            }
            uint32_t bh[8][2];
            const int kcb = ks * 16 + ((lane & 8) ? 8 : 0);
            #pragma unroll
            for (int nt4 = 0; nt4 < 4; nt4++) {
                int n = wn + nt4 * 16 + ((lane & 7) | ((lane & 16) ? 8 : 0));
                uint32_t off = (uint32_t)(n * ASTRIDE + kcb) * 2;
                ldsm_x4(bh[2 * nt4][0], bh[2 * nt4][1], bh[2 * nt4 + 1][0], bh[2 * nt4 + 1][1],
                        uBh + off);
            }
            #pragma unroll
            for (int mt = 0; mt < 2; mt++)
                #pragma unroll
                for (int nt = 0; nt < 8; nt++)
                    mma_f16(c[mt][nt], ah[mt], bh[nt]);
        }
        __syncthreads();
    }

    #pragma unroll
    for (int mt = 0; mt < 2; mt++) {
        int gr0 = row0 + wm + mt * 16 + g;
        int gr1 = gr0 + 8;
        #pragma unroll
        for (int nt = 0; nt < 8; nt++) {
            int cc = wn + nt * 8 + 2 * tig;
            if (gr0 < M) *(__half2*)(C + (size_t)gr0 * 128 + cc) = __floats2half2_rn(c[mt][nt][0], c[mt][nt][1]);
            if (gr1 < M) *(__half2*)(C + (size_t)gr1 * 128 + cc) = __floats2half2_rn(c[mt][nt][2], c[mt][nt][3]);
        }
    }
}

__global__ __launch_bounds__(256) void gemm_f32A(const float* __restrict__ A,
                                                 const __half* __restrict__ Bh,
                                                 __half* __restrict__ C, int M, int K) {
    gemm_body<true>(A, Bh, C, M, K);
}
__global__ __launch_bounds__(256) void gemm_f16A(const __half* __restrict__ Ah,
                                                 const __half* __restrict__ Bh,
                                                 __half* __restrict__ C, int M, int K) {
    gemm_body<false>(Ah, Bh, C, M, K);
}

// ---------------- aggregation: one warp per node, CSR gather of fp16 rows ----------------
__device__ __forceinline__ float4 load_row4(const __half* __restrict__ in, int node, int lane) {
    uint2 pv = ((const uint2*)(in + (size_t)node * HIDF))[lane];  // 4 halves
    float2 fa = __half22float2(*(__half2*)&pv.x);
    float2 fb = __half22float2(*(__half2*)&pv.y);
    return make_float4(fa.x, fa.y, fb.x, fb.y);
}

// Layer 1: relu, emit fp16 (feeds gemm_f16A)
__global__ __launch_bounds__(256) void k_agg_f16(const __half* __restrict__ in,
                                                 __half* __restrict__ outh,
                                                 const float* __restrict__ bias) {
    int warp = (blockIdx.x * blockDim.x + threadIdx.x) >> 5;
    int lane = threadIdx.x & 31;
    if (warp >= NN) return;
    float dn = g_dinv[warp];
    float4 v = load_row4(in, warp, lane);
    float s = dn * dn;
    float4 acc = make_float4(v.x * s, v.y * s, v.z * s, v.w * s);
    int beg = g_rowptr[warp], end = g_rowptr[warp + 1];
    for (int j = beg; j < end; j++) {
        int src = g_src[j];
        float w = g_dinv[src] * dn;
        float4 u = load_row4(in, src, lane);
        acc.x += u.x * w; acc.y += u.y * w;
        acc.z += u.z * w; acc.w += u.w * w;
    }
    float4 b = ((const float4*)bias)[lane];
    acc.x = fmaxf(acc.x + b.x, 0.f); acc.y = fmaxf(acc.y + b.y, 0.f);
    acc.z = fmaxf(acc.z + b.z, 0.f); acc.w = fmaxf(acc.w + b.w, 0.f);
    __half2 h0 = __floats2half2_rn(acc.x, acc.y);
    __half2 h1 = __floats2half2_rn(acc.z, acc.w);
    uint2 ph = make_uint2(*(uint32_t*)&h0, *(uint32_t*)&h1);
    ((uint2*)(outh + (size_t)warp * HIDF))[lane] = ph;
}

// Layer 2 + pool fused: fp32 h out, then block-level run-compressed atomic pool.
// Block = 8 warps = 8 consecutive nodes; batch sorted -> 1-2 graph runs per block.
__global__ __launch_bounds__(256) void k_agg2_pool(const __half* __restrict__ in,
                                                   float* __restrict__ out,
                                                   const float* __restrict__ bias,
                                                   const int* __restrict__ batch,
                                                   float* __restrict__ out_hs) {
    __shared__ float srow[8][HIDF];
    __shared__ int sg[8];
    int wid = threadIdx.x >> 5, lane = threadIdx.x & 31;
    int node = blockIdx.x * 8 + wid;   // NN = 6250*8, always valid
    float dn = g_dinv[node];
    float4 v = load_row4(in, node, lane);
    float s = dn * dn;
    float4 acc = make_float4(v.x * s, v.y * s, v.z * s, v.w * s);
    int beg = g_rowptr[node], end = g_rowptr[node + 1];
    for (int j = beg; j < end; j++) {
        int src = g_src[j];
        float w = g_dinv[src] * dn;
        float4 u = load_row4(in, src, lane);
        acc.x += u.x * w; acc.y += u.y * w;
        acc.z += u.z * w; acc.w += u.w * w;
    }
    float4 b = ((const float4*)bias)[lane];
    acc.x += b.x; acc.y += b.y; acc.z += b.z; acc.w += b.w;
    ((float4*)(out + (size_t)node * HIDF))[lane] = acc;
    ((float4*)&srow[wid][0])[lane] = acc;
    if (lane == 0) sg[wid] = batch[node];
    __syncthreads();
    int t = threadIdx.x;
    if (t < HIDF) {
        float a = 0.f;
        int g = sg[0];
        #pragma unroll
        for (int r = 0; r < 8; r++) {
            int gr = sg[r];
            if (gr != g) {
                atomicAdd(&out_hs[g * HIDF + t], a);
                a = 0.f;
                g = gr;
            }
            a += srow[r][t];
        }
        atomicAdd(&out_hs[g * HIDF + t], a);
    }
}

// ---------------- launch ----------------
extern "C" void kernel_launch(void* const* d_in, const int* in_sizes, int n_in,
                              void* d_out, int out_size) {
    const float* x     = (const float*)d_in[0];
    const float* W1    = (const float*)d_in[1];
    const float* b1    = (const float*)d_in[2];
    const float* W2    = (const float*)d_in[3];
    const float* b2    = (const float*)d_in[4];
    const int*   ei    = (const int*)d_in[5];
    const int*   batch = (const int*)d_in[6];
    const int* row = ei;        // edge_index[0] = source
    const int* col = ei + NE;   // edge_index[1] = target

    float* out_hs = (float*)d_out;
    float* out_h  = (float*)d_out + (size_t)NG * HIDF;

    __half *g1, *h1h, *w1h, *w2h;
    cudaGetSymbolAddress((void**)&g1, g_g1);
    cudaGetSymbolAddress((void**)&h1h, g_h1h);
    cudaGetSymbolAddress((void**)&w1h, g_w1h);
    cudaGetSymbolAddress((void**)&w2h, g_w2h);

    cudaFuncSetAttribute(k_scan, cudaFuncAttributeMaxDynamicSharedMemorySize, NN * 4);

    // fork-join streams (created per call; see round-10 note on lifetime)
    cudaStream_t s2;
    cudaStreamCreateWithFlags(&s2, cudaStreamNonBlocking);
    cudaEvent_t evFork, evJoin;
    cudaEventCreateWithFlags(&evFork, cudaEventDisableTiming);
    cudaEventCreateWithFlags(&evJoin, cudaEventDisableTiming);

    cudaEventRecord(evFork, 0);
    cudaStreamWaitEvent(s2, evFork, 0);

    // branch B (s2): CSR build (+ zero-init of out_hs inside k_scan)
    k_count<<<(NE / 2 + 255) / 256, 256, 0, s2>>>(col);
    k_scan<<<1, 1024, NN * 4, s2>>>(out_hs);
    k_fill<<<(NE / 2 + 255) / 256, 256, 0, s2>>>(row, col);
    cudaEventRecord(evJoin, s2);

    const int GEMM_GRID = (NN + 127) / 128;  // 391
    const int AGG_GRID  = (NN + 7) / 8;      // 6250

    // branch A (origin): weights + layer-1 GEMM
    k_prepw<<<256, 256>>>(W1, W2);
    gemm_f32A<<<GEMM_GRID, 256>>>(x, w1h, g1, NN, INF_);

    // join: aggregation needs CSR
    cudaStreamWaitEvent(0, evJoin, 0);
    k_agg_f16<<<AGG_GRID, 256>>>(g1, h1h, b1);

    // layer 2
    gemm_f16A<<<GEMM_GRID, 256>>>(h1h, w2h, g1, NN, HIDF);

    // layer-2 aggregation + fused pooling
    k_agg2_pool<<<AGG_GRID, 256>>>(g1, out_h, b2, batch, out_hs);
}